// round 1
// baseline (speedup 1.0000x reference)
#include <cuda_runtime.h>
#include <math.h>

#define N_NODES 100000
#define E_EDGES 1000000
#define IN_DIM  128
#define OUT_DIM 64
#define H_HEADS 2
#define HO      (H_HEADS * OUT_DIM)   // 128

#define BLK_N 32     // nodes per z-block
#define PADW  132    // padded row for W^T tile (4-way write conflict max, 16B-aligned reads)
#define PADX  34     // padded row for X^T tile

// ---- scratch (device globals: allocation-free rule) ----
__device__ float Z_SRC[(size_t)N_NODES * HO];     // 51.2 MB
__device__ float S_SRC[N_NODES * H_HEADS];
__device__ float S_DST[N_NODES * H_HEADS];
__device__ float EX[(size_t)E_EDGES * H_HEADS];   // 8 MB
__device__ float DENOM[N_NODES * H_HEADS];
__device__ float W_EFF_DST[H_HEADS * IN_DIM];

// ---- packed f32x2 helpers (FFMA2: 2x fp32 FMA throughput, PTX-only) ----
#define FMA_F32X2(d, a, b, c) \
  asm("fma.rn.f32x2 %0, %1, %2, %3;" : "=l"(d) : "l"(a), "l"(b), "l"(c))
#define PACK_F32X2(out, lo, hi) \
  asm("mov.b64 %0, {%1, %2};" : "=l"(out) : "f"(lo), "f"(hi))
#define UNPACK_F32X2(lo, hi, in) \
  asm("mov.b64 {%0, %1}, %2;" : "=f"(lo), "=f"(hi) : "l"(in))

// ---------------------------------------------------------------------------
// init: zero output accumulator + segment denominators (graph replays re-run this)
// ---------------------------------------------------------------------------
__global__ void k_init(float* __restrict__ out) {
  int i = blockIdx.x * blockDim.x + threadIdx.x;
  int stride = gridDim.x * blockDim.x;
  const int tot = N_NODES * OUT_DIM;
  for (int j = i; j < tot; j += stride) out[j] = 0.f;
  for (int j = i; j < N_NODES * H_HEADS; j += stride) DENOM[j] = 0.f;
}

// ---------------------------------------------------------------------------
// w_eff_dst[h][d] = sum_o a_d[h,o] * W_dst[h,o,d]   (z_dst never materialized)
// ---------------------------------------------------------------------------
__global__ void k_weff(const float* __restrict__ W_dst, const float* __restrict__ a_w) {
  int t = blockIdx.x * blockDim.x + threadIdx.x;
  if (t >= H_HEADS * IN_DIM) return;
  int h = t / IN_DIM, d = t % IN_DIM;
  float acc = 0.f;
  #pragma unroll 8
  for (int o = 0; o < OUT_DIM; o++)
    acc += a_w[h * 2 * OUT_DIM + OUT_DIM + o] * W_dst[(h * OUT_DIM + o) * IN_DIM + d];
  W_EFF_DST[t] = acc;
}

// ---------------------------------------------------------------------------
// s_dst[n,h] = dot(h_dst[n,:], w_eff_dst[h,:])   — warp per node, streaming
// ---------------------------------------------------------------------------
__global__ void __launch_bounds__(256) k_sdst(const float* __restrict__ h_dst) {
  int warp = (blockIdx.x * blockDim.x + threadIdx.x) >> 5;
  int lane = threadIdx.x & 31;
  if (warp >= N_NODES) return;
  const float4* xp = (const float4*)(h_dst + (size_t)warp * IN_DIM);
  float4 x = xp[lane];
  const float4* w0 = (const float4*)(W_EFF_DST);
  const float4* w1 = (const float4*)(W_EFF_DST + IN_DIM);
  float4 a = w0[lane], b = w1[lane];
  float s0 = x.x * a.x + x.y * a.y + x.z * a.z + x.w * a.w;
  float s1 = x.x * b.x + x.y * b.y + x.z * b.z + x.w * b.w;
  #pragma unroll
  for (int m = 16; m; m >>= 1) {
    s0 += __shfl_xor_sync(0xffffffffu, s0, m);
    s1 += __shfl_xor_sync(0xffffffffu, s1, m);
  }
  if (lane == 0) { S_DST[warp * 2] = s0; S_DST[warp * 2 + 1] = s1; }
}

// ---------------------------------------------------------------------------
// z_src[n,h,o] = dot(h_src[n,:], W_src[h,o,:])  +  fused s_src[n,h] reduction.
// Register-blocked: thread owns 4 ho x 8 nodes (4 node-pairs as f32x2).
// 128 threads/block, 32 nodes/block, W^T + X^T staged in smem.
// ---------------------------------------------------------------------------
__global__ void __launch_bounds__(128) k_zsrc(const float* __restrict__ h_src,
                                              const float* __restrict__ W_src,
                                              const float* __restrict__ a_w) {
  extern __shared__ float sm[];
  float* Wt = sm;                       // [IN_DIM][PADW]  Wt[d][ho]
  float* Xt = sm + IN_DIM * PADW;       // [IN_DIM][PADX]  Xt[d][n_local]
  const int t = threadIdx.x;
  const int nbase = blockIdx.x * BLK_N;

  // stage W transposed (one-time, ~4-way padded write conflict)
  #pragma unroll 4
  for (int i = t; i < HO * IN_DIM; i += 128) {
    int ho = i >> 7, d = i & 127;
    Wt[d * PADW + ho] = W_src[i];
  }
  // stage X transposed
  #pragma unroll 4
  for (int i = t; i < BLK_N * IN_DIM; i += 128) {
    int n = i >> 7, d = i & 127;
    Xt[d * PADX + n] = h_src[(size_t)(nbase + n) * IN_DIM + d];
  }
  __syncthreads();

  const int ng = t >> 5;     // node group == warp id: nodes ng*8 .. ng*8+7
  const int hg = t & 31;     // ho group: ho = hg*4 + k
  const int xb = ng * 8;

  unsigned long long acc[4][4];   // [k][node-pair], f32x2 packed over (even,odd) node
  #pragma unroll
  for (int k = 0; k < 4; k++)
    #pragma unroll
    for (int j = 0; j < 4; j++) acc[k][j] = 0ull;

  #pragma unroll 2
  for (int d = 0; d < IN_DIM; d++) {
    float4 w = *(const float4*)&Wt[d * PADW + hg * 4];
    unsigned long long w2[4];
    PACK_F32X2(w2[0], w.x, w.x);
    PACK_F32X2(w2[1], w.y, w.y);
    PACK_F32X2(w2[2], w.z, w.z);
    PACK_F32X2(w2[3], w.w, w.w);
    const unsigned long long* xr = (const unsigned long long*)&Xt[d * PADX + xb];
    #pragma unroll
    for (int jp = 0; jp < 4; jp++) {
      unsigned long long xp = xr[jp];   // LDS.64, warp-broadcast
      FMA_F32X2(acc[0][jp], xp, w2[0], acc[0][jp]);
      FMA_F32X2(acc[1][jp], xp, w2[1], acc[1][jp]);
      FMA_F32X2(acc[2][jp], xp, w2[2], acc[2][jp]);
      FMA_F32X2(acc[3][jp], xp, w2[3], acc[3][jp]);
    }
  }

  float za[4][8];
  #pragma unroll
  for (int k = 0; k < 4; k++)
    #pragma unroll
    for (int jp = 0; jp < 4; jp++)
      UNPACK_F32X2(za[k][2 * jp], za[k][2 * jp + 1], acc[k][jp]);

  const int h = hg >> 4;                                   // head of this thread's ho range
  const float4 av = *(const float4*)&a_w[h * 2 * OUT_DIM + (hg & 15) * 4];  // a_src weights

  #pragma unroll
  for (int j = 0; j < 8; j++) {
    int n = nbase + xb + j;
    float4 v = make_float4(za[0][j], za[1][j], za[2][j], za[3][j]);
    *(float4*)&Z_SRC[(size_t)n * HO + hg * 4] = v;
    // fused s_src: reduce a_s . z over o within each 16-lane (per-head) half
    float ps = av.x * v.x + av.y * v.y + av.z * v.z + av.w * v.w;
    #pragma unroll
    for (int m = 8; m; m >>= 1) ps += __shfl_xor_sync(0xffffffffu, ps, m);
    if ((hg & 15) == 0) S_SRC[n * 2 + h] = ps;
  }
}

// ---------------------------------------------------------------------------
// edge pass 1: e = leaky_relu(s_src[src]+s_dst[dst]); ex = exp(e) (max-free
// softmax — |e| <~ 8 so no overflow); accumulate segment denominators.
// ---------------------------------------------------------------------------
__global__ void k_edge1(const int* __restrict__ src_idx, const int* __restrict__ dst_idx) {
  int e = blockIdx.x * blockDim.x + threadIdx.x;
  if (e >= E_EDGES) return;
  int s = src_idx[e], d = dst_idx[e];
  float2 ss = *(const float2*)&S_SRC[s * 2];
  float2 sd = *(const float2*)&S_DST[d * 2];
  float e0 = ss.x + sd.x; e0 = e0 > 0.f ? e0 : 0.01f * e0;
  float e1 = ss.y + sd.y; e1 = e1 > 0.f ? e1 : 0.01f * e1;
  float x0 = expf(e0), x1 = expf(e1);
  *(float2*)&EX[(size_t)e * 2] = make_float2(x0, x1);
  atomicAdd(&DENOM[d * 2 + 0], x0);
  atomicAdd(&DENOM[d * 2 + 1], x1);
}

// ---------------------------------------------------------------------------
// edge pass 2: warp per edge. Gather z_src[src] (512B), scale per-head by
// alpha, combine heads via shfl, scatter with red.global.add.v4.f32.
// ---------------------------------------------------------------------------
__global__ void __launch_bounds__(256) k_edge2(const int* __restrict__ src_idx,
                                               const int* __restrict__ dst_idx,
                                               float* __restrict__ out) {
  int warp = (blockIdx.x * blockDim.x + threadIdx.x) >> 5;
  int lane = threadIdx.x & 31;
  if (warp >= E_EDGES) return;
  int s = __ldg(&src_idx[warp]);
  int d = __ldg(&dst_idx[warp]);
  float2 ex  = *(const float2*)&EX[(size_t)warp * 2];
  float2 den = *(const float2*)&DENOM[d * 2];
  float a0 = ex.x / den.x;
  float a1 = ex.y / den.y;

  float4 z = *(const float4*)&Z_SRC[(size_t)s * HO + lane * 4];
  float al = (lane < 16) ? a0 : a1;
  float4 v;
  v.x = z.x * al; v.y = z.y * al; v.z = z.z * al; v.w = z.w * al;
  // sum the two heads: lane L (<16, h0, o=L*4) pairs with lane L+16 (h1, same o)
  v.x += __shfl_xor_sync(0xffffffffu, v.x, 16);
  v.y += __shfl_xor_sync(0xffffffffu, v.y, 16);
  v.z += __shfl_xor_sync(0xffffffffu, v.z, 16);
  v.w += __shfl_xor_sync(0xffffffffu, v.w, 16);
  if (lane < 16) {
    float* p = out + (size_t)d * OUT_DIM + lane * 4;
    asm volatile("red.global.add.v4.f32 [%0], {%1, %2, %3, %4};"
                 :: "l"(p), "f"(v.x), "f"(v.y), "f"(v.z), "f"(v.w) : "memory");
  }
}

// ---------------------------------------------------------------------------
extern "C" void kernel_launch(void* const* d_in, const int* in_sizes, int n_in,
                              void* d_out, int out_size) {
  const float* h_src  = (const float*)d_in[0];
  const float* h_dst  = (const float*)d_in[1];
  const float* W_src  = (const float*)d_in[2];
  const float* W_dst  = (const float*)d_in[3];
  const float* a_w    = (const float*)d_in[4];
  const int*   src_ix = (const int*)d_in[5];
  const int*   dst_ix = (const int*)d_in[6];
  float* out = (float*)d_out;

  const int smem_zsrc = (IN_DIM * PADW + IN_DIM * PADX) * (int)sizeof(float); // 84992 B
  cudaFuncSetAttribute(k_zsrc, cudaFuncAttributeMaxDynamicSharedMemorySize, smem_zsrc);

  k_init<<<512, 256>>>(out);
  k_weff<<<1, 256>>>(W_dst, a_w);
  k_sdst<<<N_NODES / 8, 256>>>(h_dst);
  k_zsrc<<<N_NODES / BLK_N, 128, smem_zsrc>>>(h_src, W_src, a_w);
  k_edge1<<<(E_EDGES + 255) / 256, 256>>>(src_ix, dst_ix);
  k_edge2<<<E_EDGES / 8, 256>>>(src_ix, dst_ix, out);
}

// round 2
// speedup vs baseline: 1.7806x; 1.7806x over previous
#include <cuda_runtime.h>
#include <math.h>

#define N_NODES 100000
#define E_EDGES 1000000
#define IN_DIM  128
#define OUT_DIM 64
#define H_HEADS 2
#define HO      (H_HEADS * OUT_DIM)   // 128

#define BLK_N 64     // nodes per z-block
#define PADW  132    // padded row for W^T tile
#define PADX  72     // padded row for X^T tile (>= BLK_N, stride 8 mod 32 -> 4-way max)
#define CAP   64     // max degree slots per dst (Poisson(10): P(deg>=64) ~ 1e-40)

// ---- scratch (device globals: allocation-free rule) ----
__device__ float  Z_SRC[(size_t)N_NODES * HO];      // 51.2 MB
__device__ float  S_SRC[N_NODES * H_HEADS];
__device__ float  S_DST[N_NODES * H_HEADS];
__device__ float  DENOM[N_NODES * H_HEADS];
__device__ float  W_EFF_DST[H_HEADS * IN_DIM];
__device__ float4 ENT[(size_t)N_NODES * CAP];       // (ex0, ex1, src-as-bits, _) 102.4 MB
__device__ int    COUNT[N_NODES];

// ---- packed f32x2 helpers ----
#define FMA_F32X2(d, a, b, c) \
  asm("fma.rn.f32x2 %0, %1, %2, %3;" : "=l"(d) : "l"(a), "l"(b), "l"(c))
#define PACK_F32X2(out, lo, hi) \
  asm("mov.b64 %0, {%1, %2};" : "=l"(out) : "f"(lo), "f"(hi))
#define UNPACK_F32X2(lo, hi, in) \
  asm("mov.b64 {%0, %1}, %2;" : "=f"(lo), "=f"(hi) : "l"(in))

// ---------------------------------------------------------------------------
// init: zero per-replay accumulators (DENOM + COUNT). Output needs no zeroing:
// k_edge2b writes every dst node unconditionally.
// ---------------------------------------------------------------------------
__global__ void k_init() {
  int i = blockIdx.x * blockDim.x + threadIdx.x;
  int stride = gridDim.x * blockDim.x;
  for (int j = i; j < N_NODES * H_HEADS; j += stride) DENOM[j] = 0.f;
  for (int j = i; j < N_NODES; j += stride) COUNT[j] = 0;
}

// ---------------------------------------------------------------------------
// w_eff_dst[h][d] = sum_o a_d[h,o] * W_dst[h,o,d]   (z_dst never materialized)
// ---------------------------------------------------------------------------
__global__ void k_weff(const float* __restrict__ W_dst, const float* __restrict__ a_w) {
  int t = blockIdx.x * blockDim.x + threadIdx.x;
  if (t >= H_HEADS * IN_DIM) return;
  int h = t / IN_DIM, d = t % IN_DIM;
  float acc = 0.f;
  #pragma unroll 8
  for (int o = 0; o < OUT_DIM; o++)
    acc += a_w[h * 2 * OUT_DIM + OUT_DIM + o] * W_dst[(h * OUT_DIM + o) * IN_DIM + d];
  W_EFF_DST[t] = acc;
}

// ---------------------------------------------------------------------------
// s_dst[n,h] = dot(h_dst[n,:], w_eff_dst[h,:])   — warp per node, streaming
// ---------------------------------------------------------------------------
__global__ void __launch_bounds__(256) k_sdst(const float* __restrict__ h_dst) {
  int warp = (blockIdx.x * blockDim.x + threadIdx.x) >> 5;
  int lane = threadIdx.x & 31;
  if (warp >= N_NODES) return;
  const float4* xp = (const float4*)(h_dst + (size_t)warp * IN_DIM);
  float4 x = xp[lane];
  const float4* w0 = (const float4*)(W_EFF_DST);
  const float4* w1 = (const float4*)(W_EFF_DST + IN_DIM);
  float4 a = w0[lane], b = w1[lane];
  float s0 = x.x * a.x + x.y * a.y + x.z * a.z + x.w * a.w;
  float s1 = x.x * b.x + x.y * b.y + x.z * b.z + x.w * b.w;
  #pragma unroll
  for (int m = 16; m; m >>= 1) {
    s0 += __shfl_xor_sync(0xffffffffu, s0, m);
    s1 += __shfl_xor_sync(0xffffffffu, s1, m);
  }
  if (lane == 0) { S_DST[warp * 2] = s0; S_DST[warp * 2 + 1] = s1; }
}

// ---------------------------------------------------------------------------
// z_src[n,h,o] = dot(h_src[n,:], W_src[h,o,:])  +  fused s_src[n,h] reduction.
// 256 threads, 64 nodes/block. Thread owns 4 ho x 8 nodes (f32x2 node pairs).
// smem = 67.6KB (W^T) + 36.9KB (X^T) = 102KB -> 2 blocks/SM = 16 warps/SM.
// ---------------------------------------------------------------------------
__global__ void __launch_bounds__(256, 2) k_zsrc(const float* __restrict__ h_src,
                                                 const float* __restrict__ W_src,
                                                 const float* __restrict__ a_w) {
  extern __shared__ float sm[];
  float* Wt = sm;                       // [IN_DIM][PADW]  Wt[d][ho]
  float* Xt = sm + IN_DIM * PADW;       // [IN_DIM][PADX]  Xt[d][n_local]
  const int t = threadIdx.x;
  const int nbase = blockIdx.x * BLK_N;

  // stage W transposed
  #pragma unroll 4
  for (int i = t; i < HO * IN_DIM; i += 256) {
    int ho = i >> 7, d = i & 127;
    Wt[d * PADW + ho] = W_src[i];
  }
  // stage X transposed (guard tail block)
  #pragma unroll 4
  for (int i = t; i < BLK_N * IN_DIM; i += 256) {
    int n = i >> 7, d = i & 127;
    int gn = nbase + n;
    Xt[d * PADX + n] = (gn < N_NODES) ? h_src[(size_t)gn * IN_DIM + d] : 0.f;
  }
  __syncthreads();

  const int ng = t >> 5;     // warp id: nodes ng*8 .. ng*8+7
  const int hg = t & 31;     // lane: ho = hg*4 + k
  const int xb = ng * 8;

  unsigned long long acc[4][4];
  #pragma unroll
  for (int k = 0; k < 4; k++)
    #pragma unroll
    for (int j = 0; j < 4; j++) acc[k][j] = 0ull;

  #pragma unroll 4
  for (int d = 0; d < IN_DIM; d++) {
    float4 w = *(const float4*)&Wt[d * PADW + hg * 4];
    unsigned long long w2[4];
    PACK_F32X2(w2[0], w.x, w.x);
    PACK_F32X2(w2[1], w.y, w.y);
    PACK_F32X2(w2[2], w.z, w.z);
    PACK_F32X2(w2[3], w.w, w.w);
    const unsigned long long* xr = (const unsigned long long*)&Xt[d * PADX + xb];
    #pragma unroll
    for (int jp = 0; jp < 4; jp++) {
      unsigned long long xp = xr[jp];   // LDS.64, warp-broadcast
      FMA_F32X2(acc[0][jp], xp, w2[0], acc[0][jp]);
      FMA_F32X2(acc[1][jp], xp, w2[1], acc[1][jp]);
      FMA_F32X2(acc[2][jp], xp, w2[2], acc[2][jp]);
      FMA_F32X2(acc[3][jp], xp, w2[3], acc[3][jp]);
    }
  }

  float za[4][8];
  #pragma unroll
  for (int k = 0; k < 4; k++)
    #pragma unroll
    for (int jp = 0; jp < 4; jp++)
      UNPACK_F32X2(za[k][2 * jp], za[k][2 * jp + 1], acc[k][jp]);

  const int h = hg >> 4;
  const float4 av = *(const float4*)&a_w[h * 2 * OUT_DIM + (hg & 15) * 4];

  #pragma unroll
  for (int j = 0; j < 8; j++) {
    int n = nbase + xb + j;
    float4 v = make_float4(za[0][j], za[1][j], za[2][j], za[3][j]);
    float ps = av.x * v.x + av.y * v.y + av.z * v.z + av.w * v.w;
    #pragma unroll
    for (int m = 8; m; m >>= 1) ps += __shfl_xor_sync(0xffffffffu, ps, m);
    if (n < N_NODES) {
      *(float4*)&Z_SRC[(size_t)n * HO + hg * 4] = v;
      if ((hg & 15) == 0) S_SRC[n * 2 + h] = ps;
    }
  }
}

// ---------------------------------------------------------------------------
// edge pass: e = leaky_relu(s_src[src]+s_dst[dst]); ex = exp(e) (max-free,
// |e| <~ 8). Grab a CSR slot via one atomic, store (ex0,ex1,src) as one 16B
// entry, accumulate softmax denominators.
// ---------------------------------------------------------------------------
__global__ void k_edge1(const int* __restrict__ src_idx, const int* __restrict__ dst_idx) {
  int e = blockIdx.x * blockDim.x + threadIdx.x;
  if (e >= E_EDGES) return;
  int s = src_idx[e], d = dst_idx[e];
  float2 ss = *(const float2*)&S_SRC[s * 2];
  float2 sd = *(const float2*)&S_DST[d * 2];
  float e0 = ss.x + sd.x; e0 = e0 > 0.f ? e0 : 0.01f * e0;
  float e1 = ss.y + sd.y; e1 = e1 > 0.f ? e1 : 0.01f * e1;
  float x0 = expf(e0), x1 = expf(e1);
  int c = atomicAdd(&COUNT[d], 1);
  if (c < CAP) {
    ENT[(size_t)d * CAP + c] = make_float4(x0, x1, __int_as_float(s), 0.f);
    atomicAdd(&DENOM[d * 2 + 0], x0);
    atomicAdd(&DENOM[d * 2 + 1], x1);
  }
}

// ---------------------------------------------------------------------------
// gather pass: warp per dst node. Register-accumulate alpha-weighted z over
// the node's edge list; combine heads via shfl; ONE plain 256B store per node.
// No output atomics at all.
// ---------------------------------------------------------------------------
__global__ void __launch_bounds__(256) k_edge2b(float* __restrict__ out) {
  int node = (blockIdx.x * blockDim.x + threadIdx.x) >> 5;
  int lane = threadIdx.x & 31;
  if (node >= N_NODES) return;

  int deg = COUNT[node];
  deg = deg < CAP ? deg : CAP;
  float2 den = *(const float2*)&DENOM[node * 2];
  float inv0 = 1.f / den.x, inv1 = 1.f / den.y;   // unused when deg==0

  float4 acc = make_float4(0.f, 0.f, 0.f, 0.f);
  const size_t base = (size_t)node * CAP;

  for (int c0 = 0; c0 < deg; c0 += 32) {
    int c = c0 + lane;
    float4 ent = make_float4(0.f, 0.f, 0.f, 0.f);
    if (c < deg) ent = ENT[base + c];
    int cnt = deg - c0; cnt = cnt < 32 ? cnt : 32;
    for (int j = 0; j < cnt; j++) {
      float ex0 = __shfl_sync(0xffffffffu, ent.x, j);
      float ex1 = __shfl_sync(0xffffffffu, ent.y, j);
      int   s   = __shfl_sync(0xffffffffu, __float_as_int(ent.z), j);
      float al  = (lane < 16) ? ex0 * inv0 : ex1 * inv1;
      float4 z = *(const float4*)&Z_SRC[(size_t)s * HO + lane * 4];
      acc.x = fmaf(al, z.x, acc.x);
      acc.y = fmaf(al, z.y, acc.y);
      acc.z = fmaf(al, z.z, acc.z);
      acc.w = fmaf(al, z.w, acc.w);
    }
  }

  // combine the two heads: lane L (<16, h0) pairs with lane L+16 (h1, same o)
  acc.x += __shfl_xor_sync(0xffffffffu, acc.x, 16);
  acc.y += __shfl_xor_sync(0xffffffffu, acc.y, 16);
  acc.z += __shfl_xor_sync(0xffffffffu, acc.z, 16);
  acc.w += __shfl_xor_sync(0xffffffffu, acc.w, 16);
  if (lane < 16)
    *(float4*)&out[(size_t)node * OUT_DIM + lane * 4] = acc;
}

// ---------------------------------------------------------------------------
extern "C" void kernel_launch(void* const* d_in, const int* in_sizes, int n_in,
                              void* d_out, int out_size) {
  const float* h_src  = (const float*)d_in[0];
  const float* h_dst  = (const float*)d_in[1];
  const float* W_src  = (const float*)d_in[2];
  const float* W_dst  = (const float*)d_in[3];
  const float* a_w    = (const float*)d_in[4];
  const int*   src_ix = (const int*)d_in[5];
  const int*   dst_ix = (const int*)d_in[6];
  float* out = (float*)d_out;

  const int smem_zsrc = (IN_DIM * PADW + IN_DIM * PADX) * (int)sizeof(float); // 104448 B
  cudaFuncSetAttribute(k_zsrc, cudaFuncAttributeMaxDynamicSharedMemorySize, smem_zsrc);

  k_init<<<256, 256>>>();
  k_weff<<<1, 256>>>(W_dst, a_w);
  k_sdst<<<N_NODES / 8, 256>>>(h_dst);
  k_zsrc<<<(N_NODES + BLK_N - 1) / BLK_N, 256, smem_zsrc>>>(h_src, W_src, a_w);
  k_edge1<<<(E_EDGES + 255) / 256, 256>>>(src_ix, dst_ix);
  k_edge2b<<<(N_NODES * 32 + 255) / 256, 256>>>(out);
}

// round 4
// speedup vs baseline: 2.2159x; 1.2445x over previous
#include <cuda_runtime.h>
#include <math.h>
#include <stdint.h>

#define N_NODES 100000
#define E_EDGES 1000000
#define IN_DIM  128
#define OUT_DIM 64
#define H_HEADS 2
#define HO      (H_HEADS * OUT_DIM)   // 128

#define BLK_M   64     // nodes per GEMM block (4 warps x m16)
#define CAP     64     // max degree slots per dst (Poisson(10): P(deg>=64) ~ 1e-40)

#define PAD_A   132    // X tile row pad (floats) -> conflict-free A-frag loads
#define PAD_B   136    // W tile row pad (floats)

// ---- scratch (device globals: allocation-free rule) ----
__device__ float  Z_SRC[(size_t)N_NODES * HO];      // 51.2 MB
__device__ float  S_SRC[N_NODES * H_HEADS];
__device__ float  S_DST[N_NODES * H_HEADS];
__device__ float  DENOM[N_NODES * H_HEADS];
__device__ float  W_EFF_SRC[H_HEADS * IN_DIM];
__device__ float  W_EFF_DST[H_HEADS * IN_DIM];
__device__ float  W_RE[HO * IN_DIM];                // W_src tf32-rounded, frag-pair order
__device__ float4 ENT[(size_t)N_NODES * CAP];       // (ex0, ex1, src-as-bits, _)
__device__ int    COUNT[N_NODES];

__device__ __forceinline__ float tf32_rna(float x) {
  uint32_t y;
  asm("cvt.rna.tf32.f32 %0, %1;" : "=r"(y) : "f"(x));
  return __uint_as_float(y);
}

// m16n8k8 tf32 MMA (sm_80+ PTX -- no 'a' feature needed)
__device__ __forceinline__ void mma_tf32(float d[4],
                                         uint32_t a0, uint32_t a1, uint32_t a2, uint32_t a3,
                                         uint32_t b0, uint32_t b1) {
  asm volatile("mma.sync.aligned.m16n8k8.row.col.f32.tf32.tf32.f32 "
               "{%0,%1,%2,%3}, {%4,%5,%6,%7}, {%8,%9}, {%0,%1,%2,%3};"
               : "+f"(d[0]), "+f"(d[1]), "+f"(d[2]), "+f"(d[3])
               : "r"(a0), "r"(a1), "r"(a2), "r"(a3), "r"(b0), "r"(b1));
}

// ---------------------------------------------------------------------------
// init: zero per-replay accumulators (DENOM + COUNT)
// ---------------------------------------------------------------------------
__global__ void k_init() {
  int i = blockIdx.x * blockDim.x + threadIdx.x;
  int stride = gridDim.x * blockDim.x;
  for (int j = i; j < N_NODES * H_HEADS; j += stride) DENOM[j] = 0.f;
  for (int j = i; j < N_NODES; j += stride) COUNT[j] = 0;
}

// ---------------------------------------------------------------------------
// w_eff[h][d]: src uses a_w[h,:OUT], dst uses a_w[h,OUT:]  (scores stay fp32)
// ---------------------------------------------------------------------------
__global__ void k_weff(const float* __restrict__ W_src, const float* __restrict__ W_dst,
                       const float* __restrict__ a_w) {
  int t = blockIdx.x * blockDim.x + threadIdx.x;
  if (t >= H_HEADS * IN_DIM) return;
  int h = t / IN_DIM, d = t % IN_DIM;
  float as_acc = 0.f, ad_acc = 0.f;
  #pragma unroll 8
  for (int o = 0; o < OUT_DIM; o++) {
    as_acc += a_w[h * 2 * OUT_DIM + o]           * W_src[(h * OUT_DIM + o) * IN_DIM + d];
    ad_acc += a_w[h * 2 * OUT_DIM + OUT_DIM + o] * W_dst[(h * OUT_DIM + o) * IN_DIM + d];
  }
  W_EFF_SRC[t] = as_acc;
  W_EFF_DST[t] = ad_acc;
}

// ---------------------------------------------------------------------------
// W reorder: tf32-round + pack (b0,b1) frag pairs adjacent:
// col' = (k/8)*8 + (k%4)*2 + ((k%8)>>2)  so thread q loads float2 = (W[n][8kk+q], W[n][8kk+q+4])
// ---------------------------------------------------------------------------
__global__ void k_wre(const float* __restrict__ W_src) {
  int i = blockIdx.x * blockDim.x + threadIdx.x;
  if (i >= HO * IN_DIM) return;
  int n = i >> 7, k = i & 127;
  int col = (k >> 3) * 8 + (k & 3) * 2 + ((k & 7) >> 2);
  W_RE[n * IN_DIM + col] = tf32_rna(W_src[i]);
}

// ---------------------------------------------------------------------------
// scores: s_src[n,h] and s_dst[n,h] via w_eff dots — warp per node, fp32 exact
// ---------------------------------------------------------------------------
__global__ void __launch_bounds__(256) k_scores(const float* __restrict__ h_src,
                                                const float* __restrict__ h_dst) {
  int warp = (blockIdx.x * blockDim.x + threadIdx.x) >> 5;
  int lane = threadIdx.x & 31;
  if (warp >= N_NODES) return;
  float4 xs = ((const float4*)(h_src + (size_t)warp * IN_DIM))[lane];
  float4 xd = ((const float4*)(h_dst + (size_t)warp * IN_DIM))[lane];
  float4 ws0 = ((const float4*)W_EFF_SRC)[lane];
  float4 ws1 = ((const float4*)(W_EFF_SRC + IN_DIM))[lane];
  float4 wd0 = ((const float4*)W_EFF_DST)[lane];
  float4 wd1 = ((const float4*)(W_EFF_DST + IN_DIM))[lane];
  float s0 = xs.x*ws0.x + xs.y*ws0.y + xs.z*ws0.z + xs.w*ws0.w;
  float s1 = xs.x*ws1.x + xs.y*ws1.y + xs.z*ws1.z + xs.w*ws1.w;
  float d0 = xd.x*wd0.x + xd.y*wd0.y + xd.z*wd0.z + xd.w*wd0.w;
  float d1 = xd.x*wd1.x + xd.y*wd1.y + xd.z*wd1.z + xd.w*wd1.w;
  #pragma unroll
  for (int m = 16; m; m >>= 1) {
    s0 += __shfl_xor_sync(0xffffffffu, s0, m);
    s1 += __shfl_xor_sync(0xffffffffu, s1, m);
    d0 += __shfl_xor_sync(0xffffffffu, d0, m);
    d1 += __shfl_xor_sync(0xffffffffu, d1, m);
  }
  if (lane == 0) {
    S_SRC[warp * 2] = s0; S_SRC[warp * 2 + 1] = s1;
    S_DST[warp * 2] = d0; S_DST[warp * 2 + 1] = d1;
  }
}

// ---------------------------------------------------------------------------
// z_src via tensor-core mma.sync tf32. Block: 64 nodes x 128 ho x K=128.
// 4 warps, each m16 x n128 (16 m16n8k8 tiles). Fused s_src epilogue.
// smem: a_s(512B) + X[64][132] (33.8KB) + Wre[128][136] (69.6KB) = ~102KB.
// ---------------------------------------------------------------------------
#define SM_AS   0
#define SM_A    512
#define SM_B    (SM_A + BLK_M * PAD_A * 4)              // 34304
#define SM_TOT  (SM_B + HO * PAD_B * 4)                 // 103936

__global__ void __launch_bounds__(128, 2) k_zsrc_mma(const float* __restrict__ h_src,
                                                     const float* __restrict__ a_w) {
  extern __shared__ char sm[];
  float* as_sm = (float*)(sm + SM_AS);
  float* Asm   = (float*)(sm + SM_A);   // [BLK_M][PAD_A]
  float* Bsm   = (float*)(sm + SM_B);   // [HO][PAD_B]
  const int tid = threadIdx.x;
  const int nbase = blockIdx.x * BLK_M;

  if (tid < HO) as_sm[tid] = a_w[(tid >> 6) * 2 * OUT_DIM + (tid & 63)];

  // stage X (tf32-rounded), zero-pad rows past N_NODES
  #pragma unroll
  for (int it = 0; it < (BLK_M * 32) / 128; it++) {
    int i = tid + it * 128;
    int row = i >> 5, c4 = i & 31;
    int gn = nbase + row;
    float4 v = make_float4(0.f, 0.f, 0.f, 0.f);
    if (gn < N_NODES) v = *(const float4*)&h_src[(size_t)gn * IN_DIM + c4 * 4];
    v.x = tf32_rna(v.x); v.y = tf32_rna(v.y); v.z = tf32_rna(v.z); v.w = tf32_rna(v.w);
    *(float4*)&Asm[row * PAD_A + c4 * 4] = v;
  }
  // stage W_RE (already rounded + pair-ordered)
  #pragma unroll
  for (int it = 0; it < (HO * 32) / 128; it++) {
    int i = tid + it * 128;
    int row = i >> 5, c4 = i & 31;
    *(float4*)&Bsm[row * PAD_B + c4 * 4] = *(const float4*)&W_RE[row * IN_DIM + c4 * 4];
  }
  __syncthreads();

  const int wr = tid >> 5;          // warp row: nodes wr*16 .. wr*16+15
  const int t  = tid & 31;
  const int g  = t >> 2;            // groupID
  const int q  = t & 3;

  float d[16][4];
  #pragma unroll
  for (int j = 0; j < 16; j++)
    #pragma unroll
    for (int c = 0; c < 4; c++) d[j][c] = 0.f;

  const float* Ar0 = &Asm[(wr * 16 + g) * PAD_A];
  const float* Ar1 = Ar0 + 8 * PAD_A;

  #pragma unroll 4
  for (int kk = 0; kk < 16; kk++) {
    int c = q + kk * 8;
    uint32_t a0 = __float_as_uint(Ar0[c]);
    uint32_t a1 = __float_as_uint(Ar1[c]);
    uint32_t a2 = __float_as_uint(Ar0[c + 4]);
    uint32_t a3 = __float_as_uint(Ar1[c + 4]);
    #pragma unroll
    for (int j = 0; j < 16; j++) {
      float2 b = *(const float2*)&Bsm[(g + 8 * j) * PAD_B + kk * 8 + q * 2];
      mma_tf32(d[j], a0, a1, a2, a3, __float_as_uint(b.x), __float_as_uint(b.y));
    }
  }

  // epilogue: store Z + fused s_src
  int r0 = nbase + wr * 16 + g;
  int r1 = r0 + 8;
  bool v0 = (r0 < N_NODES), v1 = (r1 < N_NODES);
  float ps00 = 0.f, ps01 = 0.f, ps10 = 0.f, ps11 = 0.f;   // [rowhalf][head]
  #pragma unroll
  for (int j = 0; j < 16; j++) {
    int col = 8 * j + q * 2;
    float w0 = as_sm[col], w1 = as_sm[col + 1];
    if (j < 8) { ps00 += w0 * d[j][0] + w1 * d[j][1]; ps10 += w0 * d[j][2] + w1 * d[j][3]; }
    else       { ps01 += w0 * d[j][0] + w1 * d[j][1]; ps11 += w0 * d[j][2] + w1 * d[j][3]; }
    if (v0) *(float2*)&Z_SRC[(size_t)r0 * HO + col] = make_float2(d[j][0], d[j][1]);
    if (v1) *(float2*)&Z_SRC[(size_t)r1 * HO + col] = make_float2(d[j][2], d[j][3]);
  }
  #pragma unroll
  for (int m = 1; m <= 2; m <<= 1) {
    ps00 += __shfl_xor_sync(0xffffffffu, ps00, m);
    ps01 += __shfl_xor_sync(0xffffffffu, ps01, m);
    ps10 += __shfl_xor_sync(0xffffffffu, ps10, m);
    ps11 += __shfl_xor_sync(0xffffffffu, ps11, m);
  }
  if (q == 0) {
    if (v0) { S_SRC[r0 * 2] = ps00; S_SRC[r0 * 2 + 1] = ps01; }
    if (v1) { S_SRC[r1 * 2] = ps10; S_SRC[r1 * 2 + 1] = ps11; }
  }
}

// NOTE: s_src from this kernel is tf32-derived; k_scores recomputes it fp32-exact
// and runs AFTER k_zsrc_mma in the launch order, overwriting S_SRC. (Launch order below.)

// ---------------------------------------------------------------------------
// edge pass: ex = exp(leaky_relu(s_src[src]+s_dst[dst])) (max-free, |e|<~8).
// Slot-grab via one atomic; 16B ENT entry; denominator accumulation.
// ---------------------------------------------------------------------------
__global__ void k_edge1(const int* __restrict__ src_idx, const int* __restrict__ dst_idx) {
  int e = blockIdx.x * blockDim.x + threadIdx.x;
  if (e >= E_EDGES) return;
  int s = src_idx[e], d = dst_idx[e];
  float2 ss = *(const float2*)&S_SRC[s * 2];
  float2 sd = *(const float2*)&S_DST[d * 2];
  float e0 = ss.x + sd.x; e0 = e0 > 0.f ? e0 : 0.01f * e0;
  float e1 = ss.y + sd.y; e1 = e1 > 0.f ? e1 : 0.01f * e1;
  float x0 = expf(e0), x1 = expf(e1);
  int c = atomicAdd(&COUNT[d], 1);
  if (c < CAP) {
    ENT[(size_t)d * CAP + c] = make_float4(x0, x1, __int_as_float(s), 0.f);
    atomicAdd(&DENOM[d * 2 + 0], x0);
    atomicAdd(&DENOM[d * 2 + 1], x1);
  }
}

// ---------------------------------------------------------------------------
// gather pass: warp per dst node; register accumulation; one 256B store/node.
// ---------------------------------------------------------------------------
__global__ void __launch_bounds__(256) k_edge2b(float* __restrict__ out) {
  int node = (blockIdx.x * blockDim.x + threadIdx.x) >> 5;
  int lane = threadIdx.x & 31;
  if (node >= N_NODES) return;

  int deg = COUNT[node];
  deg = deg < CAP ? deg : CAP;
  float2 den = *(const float2*)&DENOM[node * 2];
  float inv0 = 1.f / den.x, inv1 = 1.f / den.y;

  float4 acc = make_float4(0.f, 0.f, 0.f, 0.f);
  const size_t base = (size_t)node * CAP;

  for (int c0 = 0; c0 < deg; c0 += 32) {
    int c = c0 + lane;
    float4 ent = make_float4(0.f, 0.f, 0.f, 0.f);
    if (c < deg) ent = ENT[base + c];
    int cnt = deg - c0; cnt = cnt < 32 ? cnt : 32;
    for (int j = 0; j < cnt; j++) {
      float ex0 = __shfl_sync(0xffffffffu, ent.x, j);
      float ex1 = __shfl_sync(0xffffffffu, ent.y, j);
      int   s   = __shfl_sync(0xffffffffu, __float_as_int(ent.z), j);
      float al  = (lane < 16) ? ex0 * inv0 : ex1 * inv1;
      float4 z = *(const float4*)&Z_SRC[(size_t)s * HO + lane * 4];
      acc.x = fmaf(al, z.x, acc.x);
      acc.y = fmaf(al, z.y, acc.y);
      acc.z = fmaf(al, z.z, acc.z);
      acc.w = fmaf(al, z.w, acc.w);
    }
  }

  acc.x += __shfl_xor_sync(0xffffffffu, acc.x, 16);
  acc.y += __shfl_xor_sync(0xffffffffu, acc.y, 16);
  acc.z += __shfl_xor_sync(0xffffffffu, acc.z, 16);
  acc.w += __shfl_xor_sync(0xffffffffu, acc.w, 16);
  if (lane < 16)
    *(float4*)&out[(size_t)node * OUT_DIM + lane * 4] = acc;
}

// ---------------------------------------------------------------------------
extern "C" void kernel_launch(void* const* d_in, const int* in_sizes, int n_in,
                              void* d_out, int out_size) {
  const float* h_src  = (const float*)d_in[0];
  const float* h_dst  = (const float*)d_in[1];
  const float* W_src  = (const float*)d_in[2];
  const float* W_dst  = (const float*)d_in[3];
  const float* a_w    = (const float*)d_in[4];
  const int*   src_ix = (const int*)d_in[5];
  const int*   dst_ix = (const int*)d_in[6];
  float* out = (float*)d_out;

  cudaFuncSetAttribute(k_zsrc_mma, cudaFuncAttributeMaxDynamicSharedMemorySize, SM_TOT);

  k_init<<<256, 256>>>();
  k_weff<<<1, 256>>>(W_src, W_dst, a_w);
  k_wre<<<(HO * IN_DIM + 255) / 256, 256>>>(W_src);
  k_zsrc_mma<<<(N_NODES + BLK_M - 1) / BLK_M, 128, SM_TOT>>>(h_src, a_w);
  k_scores<<<N_NODES / 8, 256>>>(h_src, h_dst);   // fp32-exact S_SRC/S_DST (overwrites tf32 s_src)
  k_edge1<<<(E_EDGES + 255) / 256, 256>>>(src_ix, dst_ix);
  k_edge2b<<<(N_NODES * 32 + 255) / 256, 256>>>(out);
}

// round 5
// speedup vs baseline: 2.4074x; 1.0864x over previous
#include <cuda_runtime.h>
#include <cuda_fp16.h>
#include <math.h>
#include <stdint.h>

#define N_NODES 100000
#define E_EDGES 1000000
#define IN_DIM  128
#define OUT_DIM 64
#define H_HEADS 2
#define HO      (H_HEADS * OUT_DIM)   // 128

#define BLK_M   128    // nodes per GEMM block
#define CAP     64     // max degree slots per dst (Poisson(10): P(deg>=64) ~ 1e-40)
#define PAD_A   132    // X tile row pad (floats): conflict-free A-frag loads, 16B-aligned rows

// ---- scratch (device globals: allocation-free rule) ----
__device__ __half  Z_H[(size_t)N_NODES * HO];       // z_src in fp16, 25.6 MB (L2-resident)
__device__ float   S_SRC[N_NODES * H_HEADS];
__device__ float   S_DST[N_NODES * H_HEADS];
__device__ float   DENOM[N_NODES * H_HEADS];
__device__ float   W_EFF_SRC[H_HEADS * IN_DIM];
__device__ float   W_EFF_DST[H_HEADS * IN_DIM];
__device__ float2  W_FR[HO * IN_DIM / 2];           // W_src tf32-rounded, frag-major
__device__ float4  ENT[(size_t)N_NODES * CAP];      // (ex0, ex1, src-as-bits, _)
__device__ int     COUNT[N_NODES];

__device__ __forceinline__ float tf32_rna(float x) {
  uint32_t y;
  asm("cvt.rna.tf32.f32 %0, %1;" : "=r"(y) : "f"(x));
  return __uint_as_float(y);
}

// m16n8k8 tf32 MMA (sm_80+ PTX — reaches the Blackwell tensor pipe w/o 'a' features)
__device__ __forceinline__ void mma_tf32(float d[4],
                                         uint32_t a0, uint32_t a1, uint32_t a2, uint32_t a3,
                                         uint32_t b0, uint32_t b1) {
  asm volatile("mma.sync.aligned.m16n8k8.row.col.f32.tf32.tf32.f32 "
               "{%0,%1,%2,%3}, {%4,%5,%6,%7}, {%8,%9}, {%0,%1,%2,%3};"
               : "+f"(d[0]), "+f"(d[1]), "+f"(d[2]), "+f"(d[3])
               : "r"(a0), "r"(a1), "r"(a2), "r"(a3), "r"(b0), "r"(b1));
}

// ---------------------------------------------------------------------------
// init: zero per-replay accumulators (DENOM + COUNT)
// ---------------------------------------------------------------------------
__global__ void k_init() {
  int i = blockIdx.x * blockDim.x + threadIdx.x;
  int stride = gridDim.x * blockDim.x;
  for (int j = i; j < N_NODES * H_HEADS; j += stride) DENOM[j] = 0.f;
  for (int j = i; j < N_NODES; j += stride) COUNT[j] = 0;
}

// ---------------------------------------------------------------------------
// w_eff[h][d]: src uses a_w[h,:OUT], dst uses a_w[h,OUT:]  (scores stay fp32)
// ---------------------------------------------------------------------------
__global__ void k_weff(const float* __restrict__ W_src, const float* __restrict__ W_dst,
                       const float* __restrict__ a_w) {
  int t = blockIdx.x * blockDim.x + threadIdx.x;
  if (t >= H_HEADS * IN_DIM) return;
  int h = t / IN_DIM, d = t % IN_DIM;
  float as_acc = 0.f, ad_acc = 0.f;
  #pragma unroll 8
  for (int o = 0; o < OUT_DIM; o++) {
    as_acc += a_w[h * 2 * OUT_DIM + o]           * W_src[(h * OUT_DIM + o) * IN_DIM + d];
    ad_acc += a_w[h * 2 * OUT_DIM + OUT_DIM + o] * W_dst[(h * OUT_DIM + o) * IN_DIM + d];
  }
  W_EFF_SRC[t] = as_acc;
  W_EFF_DST[t] = ad_acc;
}

// ---------------------------------------------------------------------------
// W prep: tf32-round + permute into frag-major order. Fragment for warp lane
// (g,q) of tile (ntile,kk) = (W[n][k], W[n][k+4]) with n=8*ntile+g, k=8*kk+q.
// Layout: W_FR[(ntile*16 + kk)*32 + g*4 + q]  -> warp LDS.64 = contiguous 256B.
// ---------------------------------------------------------------------------
__global__ void k_wfr(const float* __restrict__ W_src) {
  int o = blockIdx.x * blockDim.x + threadIdx.x;
  if (o >= HO * IN_DIM / 2) return;
  int q = o & 3, g = (o >> 2) & 7, kk = (o >> 5) & 15, ntile = o >> 9;
  int n = ntile * 8 + g;
  int k = kk * 8 + q;
  W_FR[o] = make_float2(tf32_rna(W_src[n * IN_DIM + k]),
                        tf32_rna(W_src[n * IN_DIM + k + 4]));
}

// ---------------------------------------------------------------------------
// s_dst[n,h] = dot(h_dst[n,:], w_eff_dst[h,:])   — warp per node, fp32-exact
// ---------------------------------------------------------------------------
__global__ void __launch_bounds__(256) k_sdst(const float* __restrict__ h_dst) {
  int warp = (blockIdx.x * blockDim.x + threadIdx.x) >> 5;
  int lane = threadIdx.x & 31;
  if (warp >= N_NODES) return;
  float4 x = ((const float4*)(h_dst + (size_t)warp * IN_DIM))[lane];
  float4 a = ((const float4*)W_EFF_DST)[lane];
  float4 b = ((const float4*)(W_EFF_DST + IN_DIM))[lane];
  float s0 = x.x*a.x + x.y*a.y + x.z*a.z + x.w*a.w;
  float s1 = x.x*b.x + x.y*b.y + x.z*b.z + x.w*b.w;
  #pragma unroll
  for (int m = 16; m; m >>= 1) {
    s0 += __shfl_xor_sync(0xffffffffu, s0, m);
    s1 += __shfl_xor_sync(0xffffffffu, s1, m);
  }
  if (lane == 0) { S_DST[warp * 2] = s0; S_DST[warp * 2 + 1] = s1; }
}

// ---------------------------------------------------------------------------
// z_src via mma.sync tf32. Block: 128 nodes x 128 ho x K=128, 512 threads.
// 16 warps: wm=wid>>1 (m16 tile), wn=wid&1 (n64 half). 32 accum regs/thread.
// B staged frag-major (conflict-free LDS.64). fp32-exact s_src fused into the
// X staging loop (dot taken BEFORE tf32 rounding). Z stored as fp16.
// smem: X[128][132] (67.6KB) + W_FR copy (64KB) = 131.6KB -> 1 blk/SM, 16 warps.
// ---------------------------------------------------------------------------
#define SM_A    0
#define SM_B    (BLK_M * PAD_A * 4)                 // 67584
#define SM_TOT  (SM_B + HO * IN_DIM * 4)            // 67584 + 65536 = 133120

__global__ void __launch_bounds__(512, 1) k_zsrc_mma(const float* __restrict__ h_src) {
  extern __shared__ char sm[];
  float*  Asm = (float*)(sm + SM_A);    // [BLK_M][PAD_A]
  float2* Bfr = (float2*)(sm + SM_B);   // frag-major, 8192 entries
  const int tid  = threadIdx.x;
  const int wid  = tid >> 5;
  const int lane = tid & 31;
  const int nbase = blockIdx.x * BLK_M;

  // w_eff_src per-lane slices (for fused fp32 s_src)
  float4 ws0 = ((const float4*)W_EFF_SRC)[lane];
  float4 ws1 = ((const float4*)(W_EFF_SRC + IN_DIM))[lane];

  // stage X + fused fp32 s_src. Each warp handles one full row per iter.
  #pragma unroll
  for (int it = 0; it < (BLK_M * 32) / 512; it++) {
    int row = wid + it * 16;
    int gn = nbase + row;
    float4 v = make_float4(0.f, 0.f, 0.f, 0.f);
    if (gn < N_NODES) v = *(const float4*)&h_src[(size_t)gn * IN_DIM + lane * 4];
    float p0 = v.x*ws0.x + v.y*ws0.y + v.z*ws0.z + v.w*ws0.w;
    float p1 = v.x*ws1.x + v.y*ws1.y + v.z*ws1.z + v.w*ws1.w;
    #pragma unroll
    for (int m = 16; m; m >>= 1) {
      p0 += __shfl_xor_sync(0xffffffffu, p0, m);
      p1 += __shfl_xor_sync(0xffffffffu, p1, m);
    }
    if (lane == 0 && gn < N_NODES) { S_SRC[gn * 2] = p0; S_SRC[gn * 2 + 1] = p1; }
    v.x = tf32_rna(v.x); v.y = tf32_rna(v.y); v.z = tf32_rna(v.z); v.w = tf32_rna(v.w);
    *(float4*)&Asm[row * PAD_A + lane * 4] = v;
  }
  // stage W fragments (plain contiguous copy, already rounded + permuted)
  {
    const float4* src = (const float4*)W_FR;
    float4* dst = (float4*)Bfr;
    #pragma unroll
    for (int it = 0; it < (HO * IN_DIM / 4) / 512; it++)
      dst[tid + it * 512] = src[tid + it * 512];
  }
  __syncthreads();

  const int wm = wid >> 1;          // m-tile: nodes wm*16 .. wm*16+15
  const int wn = wid & 1;           // n-half: cols wn*64 .. wn*64+63
  const int g  = lane >> 2;
  const int q  = lane & 3;

  float d[8][4];
  #pragma unroll
  for (int j = 0; j < 8; j++)
    #pragma unroll
    for (int c = 0; c < 4; c++) d[j][c] = 0.f;

  const float* Ar0 = &Asm[(wm * 16 + g) * PAD_A];
  const float* Ar1 = Ar0 + 8 * PAD_A;

  #pragma unroll 4
  for (int kk = 0; kk < 16; kk++) {
    int c = q + kk * 8;
    uint32_t a0 = __float_as_uint(Ar0[c]);
    uint32_t a1 = __float_as_uint(Ar1[c]);
    uint32_t a2 = __float_as_uint(Ar0[c + 4]);
    uint32_t a3 = __float_as_uint(Ar1[c + 4]);
    #pragma unroll
    for (int j = 0; j < 8; j++) {
      float2 b = Bfr[((wn * 8 + j) * 16 + kk) * 32 + lane];   // contiguous 256B/warp
      mma_tf32(d[j], a0, a1, a2, a3, __float_as_uint(b.x), __float_as_uint(b.y));
    }
  }

  // epilogue: store Z as fp16
  int r0 = nbase + wm * 16 + g;
  int r1 = r0 + 8;
  bool v0 = (r0 < N_NODES), v1 = (r1 < N_NODES);
  #pragma unroll
  for (int j = 0; j < 8; j++) {
    int col = (wn * 8 + j) * 8 + q * 2;
    if (v0) *(__half2*)&Z_H[(size_t)r0 * HO + col] = __floats2half2_rn(d[j][0], d[j][1]);
    if (v1) *(__half2*)&Z_H[(size_t)r1 * HO + col] = __floats2half2_rn(d[j][2], d[j][3]);
  }
}

// ---------------------------------------------------------------------------
// edge pass: ex = exp(leaky_relu(s_src[src]+s_dst[dst])) (max-free, bounded).
// Slot-grab via one atomic; 16B ENT entry; denominator accumulation.
// ---------------------------------------------------------------------------
__global__ void k_edge1(const int* __restrict__ src_idx, const int* __restrict__ dst_idx) {
  int e = blockIdx.x * blockDim.x + threadIdx.x;
  if (e >= E_EDGES) return;
  int s = src_idx[e], d = dst_idx[e];
  float2 ss = *(const float2*)&S_SRC[s * 2];
  float2 sd = *(const float2*)&S_DST[d * 2];
  float e0 = ss.x + sd.x; e0 = e0 > 0.f ? e0 : 0.01f * e0;
  float e1 = ss.y + sd.y; e1 = e1 > 0.f ? e1 : 0.01f * e1;
  float x0 = expf(e0), x1 = expf(e1);
  int c = atomicAdd(&COUNT[d], 1);
  if (c < CAP) {
    ENT[(size_t)d * CAP + c] = make_float4(x0, x1, __int_as_float(s), 0.f);
    atomicAdd(&DENOM[d * 2 + 0], x0);
    atomicAdd(&DENOM[d * 2 + 1], x1);
  }
}

// ---------------------------------------------------------------------------
// gather pass: warp per dst node. fp16 z gather (256B/edge), fp32 accumulate,
// one 256B store per node. No output atomics.
// ---------------------------------------------------------------------------
__global__ void __launch_bounds__(256) k_edge2b(float* __restrict__ out) {
  int node = (blockIdx.x * blockDim.x + threadIdx.x) >> 5;
  int lane = threadIdx.x & 31;
  if (node >= N_NODES) return;

  int deg = COUNT[node];
  deg = deg < CAP ? deg : CAP;
  float2 den = *(const float2*)&DENOM[node * 2];
  float inv0 = 1.f / den.x, inv1 = 1.f / den.y;

  float4 acc = make_float4(0.f, 0.f, 0.f, 0.f);
  const size_t base = (size_t)node * CAP;

  for (int c0 = 0; c0 < deg; c0 += 32) {
    int c = c0 + lane;
    float4 ent = make_float4(0.f, 0.f, 0.f, 0.f);
    if (c < deg) ent = ENT[base + c];
    int cnt = deg - c0; cnt = cnt < 32 ? cnt : 32;
    for (int j = 0; j < cnt; j++) {
      float ex0 = __shfl_sync(0xffffffffu, ent.x, j);
      float ex1 = __shfl_sync(0xffffffffu, ent.y, j);
      int   s   = __shfl_sync(0xffffffffu, __float_as_int(ent.z), j);
      float al  = (lane < 16) ? ex0 * inv0 : ex1 * inv1;
      uint2 raw = *(const uint2*)&Z_H[(size_t)s * HO + lane * 4];
      float2 z01 = __half22float2(*(__half2*)&raw.x);
      float2 z23 = __half22float2(*(__half2*)&raw.y);
      acc.x = fmaf(al, z01.x, acc.x);
      acc.y = fmaf(al, z01.y, acc.y);
      acc.z = fmaf(al, z23.x, acc.z);
      acc.w = fmaf(al, z23.y, acc.w);
    }
  }

  acc.x += __shfl_xor_sync(0xffffffffu, acc.x, 16);
  acc.y += __shfl_xor_sync(0xffffffffu, acc.y, 16);
  acc.z += __shfl_xor_sync(0xffffffffu, acc.z, 16);
  acc.w += __shfl_xor_sync(0xffffffffu, acc.w, 16);
  if (lane < 16)
    *(float4*)&out[(size_t)node * OUT_DIM + lane * 4] = acc;
}

// ---------------------------------------------------------------------------
extern "C" void kernel_launch(void* const* d_in, const int* in_sizes, int n_in,
                              void* d_out, int out_size) {
  const float* h_src  = (const float*)d_in[0];
  const float* h_dst  = (const float*)d_in[1];
  const float* W_src  = (const float*)d_in[2];
  const float* W_dst  = (const float*)d_in[3];
  const float* a_w    = (const float*)d_in[4];
  const int*   src_ix = (const int*)d_in[5];
  const int*   dst_ix = (const int*)d_in[6];
  float* out = (float*)d_out;

  cudaFuncSetAttribute(k_zsrc_mma, cudaFuncAttributeMaxDynamicSharedMemorySize, SM_TOT);

  k_init<<<256, 256>>>();
  k_weff<<<1, 256>>>(W_src, W_dst, a_w);
  k_wfr<<<(HO * IN_DIM / 2 + 255) / 256, 256>>>(W_src);
  k_zsrc_mma<<<(N_NODES + BLK_M - 1) / BLK_M, 512, SM_TOT>>>(h_src);
  k_sdst<<<N_NODES / 8, 256>>>(h_dst);
  k_edge1<<<(E_EDGES + 255) / 256, 256>>>(src_ix, dst_ix);
  k_edge2b<<<(N_NODES * 32 + 255) / 256, 256>>>(out);
}

// round 6
// speedup vs baseline: 2.7083x; 1.1250x over previous
#include <cuda_runtime.h>
#include <cuda_fp16.h>
#include <math.h>
#include <stdint.h>

#define N_NODES 100000
#define E_EDGES 1000000
#define IN_DIM  128
#define OUT_DIM 64
#define H_HEADS 2
#define HO      (H_HEADS * OUT_DIM)   // 128

#define BLK_M   128    // nodes per GEMM block
#define CAP     64     // max degree slots per dst (Poisson(10): P(deg>=64) ~ 1e-40)
#define PADH    136    // X tile row pad (halves): conflict-free A-frag LDS.32

// ---- scratch (device globals: allocation-free rule) ----
__device__ __half  Z_H[(size_t)N_NODES * HO];       // z_src fp16, 25.6 MB (L2-resident)
__device__ float   S_SRC[N_NODES * H_HEADS];
__device__ float   S_DST[N_NODES * H_HEADS];
__device__ float   DENOM[N_NODES * H_HEADS];
__device__ float   W_EFF_SRC[H_HEADS * IN_DIM];
__device__ float   W_EFF_DST[H_HEADS * IN_DIM];
__device__ uint2   W_FRH[HO * IN_DIM / 4];          // W_src fp16, frag-major (4096 x 8B)
__device__ float4  ENT[(size_t)N_NODES * CAP];      // (ex0, ex1, src-as-bits, _)
__device__ int     COUNT[N_NODES];

// fp16 m16n8k16 MMA, fp32 accumulate (sm_80+ PTX -> Blackwell tensor pipe)
__device__ __forceinline__ void mma_f16(float d[4],
                                        uint32_t a0, uint32_t a1, uint32_t a2, uint32_t a3,
                                        uint32_t b0, uint32_t b1) {
  asm volatile("mma.sync.aligned.m16n8k16.row.col.f32.f16.f16.f32 "
               "{%0,%1,%2,%3}, {%4,%5,%6,%7}, {%8,%9}, {%0,%1,%2,%3};"
               : "+f"(d[0]), "+f"(d[1]), "+f"(d[2]), "+f"(d[3])
               : "r"(a0), "r"(a1), "r"(a2), "r"(a3), "r"(b0), "r"(b1));
}
__device__ __forceinline__ uint32_t h2bits(__half2 h) { return *(uint32_t*)&h; }

// ---------------------------------------------------------------------------
// init: zero per-replay accumulators (DENOM + COUNT)
// ---------------------------------------------------------------------------
__global__ void k_init() {
  int i = blockIdx.x * blockDim.x + threadIdx.x;
  int stride = gridDim.x * blockDim.x;
  for (int j = i; j < N_NODES * H_HEADS; j += stride) DENOM[j] = 0.f;
  for (int j = i; j < N_NODES; j += stride) COUNT[j] = 0;
}

// ---------------------------------------------------------------------------
// w_eff[h][d]: src uses a_w[h,:OUT], dst uses a_w[h,OUT:]  (scores stay fp32)
// ---------------------------------------------------------------------------
__global__ void k_weff(const float* __restrict__ W_src, const float* __restrict__ W_dst,
                       const float* __restrict__ a_w) {
  int t = blockIdx.x * blockDim.x + threadIdx.x;
  if (t >= H_HEADS * IN_DIM) return;
  int h = t / IN_DIM, d = t % IN_DIM;
  float as_acc = 0.f, ad_acc = 0.f;
  #pragma unroll 8
  for (int o = 0; o < OUT_DIM; o++) {
    as_acc += a_w[h * 2 * OUT_DIM + o]           * W_src[(h * OUT_DIM + o) * IN_DIM + d];
    ad_acc += a_w[h * 2 * OUT_DIM + OUT_DIM + o] * W_dst[(h * OUT_DIM + o) * IN_DIM + d];
  }
  W_EFF_SRC[t] = as_acc;
  W_EFF_DST[t] = ad_acc;
}

// ---------------------------------------------------------------------------
// W prep: fp16-round + permute frag-major for m16n8k16.
// Entry o = (tile*8 + kk)*32 + lane, lane=(g,q):
//   b0 = {W[8t+g][16kk+2q], W[..][+1]},  b1 = {W[8t+g][16kk+2q+8], W[..][+9]}
// -> warp load of one (tile,kk) fragment = contiguous 256B LDS.64.
// ---------------------------------------------------------------------------
__global__ void k_wfr(const float* __restrict__ W_src) {
  int o = blockIdx.x * blockDim.x + threadIdx.x;
  if (o >= HO * IN_DIM / 4) return;
  int lane = o & 31, kk = (o >> 5) & 7, tile = o >> 8;
  int g = lane >> 2, q = lane & 3;
  int n = tile * 8 + g;
  int k0 = kk * 16 + 2 * q;
  const float* wr = &W_src[n * IN_DIM];
  __half2 b0 = __floats2half2_rn(wr[k0],     wr[k0 + 1]);
  __half2 b1 = __floats2half2_rn(wr[k0 + 8], wr[k0 + 9]);
  W_FRH[o] = make_uint2(h2bits(b0), h2bits(b1));
}

// ---------------------------------------------------------------------------
// s_dst[n,h] = dot(h_dst[n,:], w_eff_dst[h,:])   — warp per node, fp32-exact
// ---------------------------------------------------------------------------
__global__ void __launch_bounds__(256) k_sdst(const float* __restrict__ h_dst) {
  int warp = (blockIdx.x * blockDim.x + threadIdx.x) >> 5;
  int lane = threadIdx.x & 31;
  if (warp >= N_NODES) return;
  float4 x = ((const float4*)(h_dst + (size_t)warp * IN_DIM))[lane];
  float4 a = ((const float4*)W_EFF_DST)[lane];
  float4 b = ((const float4*)(W_EFF_DST + IN_DIM))[lane];
  float s0 = x.x*a.x + x.y*a.y + x.z*a.z + x.w*a.w;
  float s1 = x.x*b.x + x.y*b.y + x.z*b.z + x.w*b.w;
  #pragma unroll
  for (int m = 16; m; m >>= 1) {
    s0 += __shfl_xor_sync(0xffffffffu, s0, m);
    s1 += __shfl_xor_sync(0xffffffffu, s1, m);
  }
  if (lane == 0) { S_DST[warp * 2] = s0; S_DST[warp * 2 + 1] = s1; }
}

// ---------------------------------------------------------------------------
// z_src via mma.sync fp16 (m16n8k16, fp32 accum — same 11-bit mantissa as
// tf32). Block: 128 nodes x 128 ho x K=128, 512 threads, 16 warps m16xn64.
// smem 67.6KB -> 2 blocks/SM (32 warps). fp32-exact s_src fused into staging
// (dot taken BEFORE fp16 rounding). Z stored fp16.
// ---------------------------------------------------------------------------
#define SMX_BYTES (BLK_M * PADH * 2)          // 34816
#define SM_TOT    (SMX_BYTES + 32768)         // 67584

__global__ void __launch_bounds__(512, 2) k_zsrc_mma(const float* __restrict__ h_src) {
  extern __shared__ char sm[];
  __half* Xs  = (__half*)sm;                  // [BLK_M][PADH] fp16
  uint2*  Bfr = (uint2*)(sm + SMX_BYTES);     // 4096 fragments, frag-major
  const int tid  = threadIdx.x;
  const int wid  = tid >> 5;
  const int lane = tid & 31;
  const int nbase = blockIdx.x * BLK_M;

  // w_eff_src per-lane slices (for fused fp32 s_src)
  float4 ws0 = ((const float4*)W_EFF_SRC)[lane];
  float4 ws1 = ((const float4*)(W_EFF_SRC + IN_DIM))[lane];

  // stage X (fp16) + fused fp32 s_src; warp handles one row per iter
  #pragma unroll
  for (int it = 0; it < (BLK_M * 32) / 512; it++) {
    int row = wid + it * 16;
    int gn = nbase + row;
    float4 v = make_float4(0.f, 0.f, 0.f, 0.f);
    if (gn < N_NODES) v = *(const float4*)&h_src[(size_t)gn * IN_DIM + lane * 4];
    float p0 = v.x*ws0.x + v.y*ws0.y + v.z*ws0.z + v.w*ws0.w;
    float p1 = v.x*ws1.x + v.y*ws1.y + v.z*ws1.z + v.w*ws1.w;
    #pragma unroll
    for (int m = 16; m; m >>= 1) {
      p0 += __shfl_xor_sync(0xffffffffu, p0, m);
      p1 += __shfl_xor_sync(0xffffffffu, p1, m);
    }
    if (lane == 0 && gn < N_NODES) { S_SRC[gn * 2] = p0; S_SRC[gn * 2 + 1] = p1; }
    __half2 h01 = __floats2half2_rn(v.x, v.y);
    __half2 h23 = __floats2half2_rn(v.z, v.w);
    *(uint2*)&Xs[row * PADH + lane * 4] = make_uint2(h2bits(h01), h2bits(h23));
  }
  // stage W fragments (32KB contiguous copy)
  {
    const uint4* src = (const uint4*)W_FRH;
    uint4* dst = (uint4*)Bfr;
    #pragma unroll
    for (int it = 0; it < 2048 / 512; it++)
      dst[tid + it * 512] = src[tid + it * 512];
  }
  __syncthreads();

  const int wm = wid >> 1;          // m-tile: nodes wm*16 .. +15
  const int wn = wid & 1;           // n-half: cols wn*64 .. +63
  const int g  = lane >> 2;
  const int q  = lane & 3;

  float d[8][4];
  #pragma unroll
  for (int j = 0; j < 8; j++)
    #pragma unroll
    for (int c = 0; c < 4; c++) d[j][c] = 0.f;

  const __half* Ar0 = &Xs[(wm * 16 + g) * PADH];
  const __half* Ar1 = Ar0 + 8 * PADH;

  #pragma unroll
  for (int kk = 0; kk < 8; kk++) {
    int c = kk * 16 + 2 * q;
    uint32_t a0 = *(const uint32_t*)&Ar0[c];
    uint32_t a1 = *(const uint32_t*)&Ar1[c];
    uint32_t a2 = *(const uint32_t*)&Ar0[c + 8];
    uint32_t a3 = *(const uint32_t*)&Ar1[c + 8];
    #pragma unroll
    for (int j = 0; j < 8; j++) {
      uint2 b = Bfr[((wn * 8 + j) * 8 + kk) * 32 + lane];   // contiguous 256B/warp
      mma_f16(d[j], a0, a1, a2, a3, b.x, b.y);
    }
  }

  // epilogue: store Z as fp16
  int r0 = nbase + wm * 16 + g;
  int r1 = r0 + 8;
  bool v0 = (r0 < N_NODES), v1 = (r1 < N_NODES);
  #pragma unroll
  for (int j = 0; j < 8; j++) {
    int col = (wn * 8 + j) * 8 + q * 2;
    if (v0) *(__half2*)&Z_H[(size_t)r0 * HO + col] = __floats2half2_rn(d[j][0], d[j][1]);
    if (v1) *(__half2*)&Z_H[(size_t)r1 * HO + col] = __floats2half2_rn(d[j][2], d[j][3]);
  }
}

// ---------------------------------------------------------------------------
// edge pass: ex = exp(leaky_relu(s_src[src]+s_dst[dst])) (max-free, bounded).
// Slot-grab via one atomic; 16B ENT entry; denominator accumulation.
// ---------------------------------------------------------------------------
__global__ void k_edge1(const int* __restrict__ src_idx, const int* __restrict__ dst_idx) {
  int e = blockIdx.x * blockDim.x + threadIdx.x;
  if (e >= E_EDGES) return;
  int s = src_idx[e], d = dst_idx[e];
  float2 ss = *(const float2*)&S_SRC[s * 2];
  float2 sd = *(const float2*)&S_DST[d * 2];
  float e0 = ss.x + sd.x; e0 = e0 > 0.f ? e0 : 0.01f * e0;
  float e1 = ss.y + sd.y; e1 = e1 > 0.f ? e1 : 0.01f * e1;
  float x0 = expf(e0), x1 = expf(e1);
  int c = atomicAdd(&COUNT[d], 1);
  if (c < CAP) {
    ENT[(size_t)d * CAP + c] = make_float4(x0, x1, __int_as_float(s), 0.f);
    atomicAdd(&DENOM[d * 2 + 0], x0);
    atomicAdd(&DENOM[d * 2 + 1], x1);
  }
}

// ---------------------------------------------------------------------------
// gather pass: warp per dst node. fp16 z gather (256B/edge), fp32 accumulate,
// one 256B store per node. No output atomics.
// ---------------------------------------------------------------------------
__global__ void __launch_bounds__(256) k_edge2b(float* __restrict__ out) {
  int node = (blockIdx.x * blockDim.x + threadIdx.x) >> 5;
  int lane = threadIdx.x & 31;
  if (node >= N_NODES) return;

  int deg = COUNT[node];
  deg = deg < CAP ? deg : CAP;
  float2 den = *(const float2*)&DENOM[node * 2];
  float inv0 = 1.f / den.x, inv1 = 1.f / den.y;

  float4 acc = make_float4(0.f, 0.f, 0.f, 0.f);
  const size_t base = (size_t)node * CAP;

  for (int c0 = 0; c0 < deg; c0 += 32) {
    int c = c0 + lane;
    float4 ent = make_float4(0.f, 0.f, 0.f, 0.f);
    if (c < deg) ent = ENT[base + c];
    int cnt = deg - c0; cnt = cnt < 32 ? cnt : 32;
    for (int j = 0; j < cnt; j++) {
      float ex0 = __shfl_sync(0xffffffffu, ent.x, j);
      float ex1 = __shfl_sync(0xffffffffu, ent.y, j);
      int   s   = __shfl_sync(0xffffffffu, __float_as_int(ent.z), j);
      float al  = (lane < 16) ? ex0 * inv0 : ex1 * inv1;
      uint2 raw = *(const uint2*)&Z_H[(size_t)s * HO + lane * 4];
      float2 z01 = __half22float2(*(__half2*)&raw.x);
      float2 z23 = __half22float2(*(__half2*)&raw.y);
      acc.x = fmaf(al, z01.x, acc.x);
      acc.y = fmaf(al, z01.y, acc.y);
      acc.z = fmaf(al, z23.x, acc.z);
      acc.w = fmaf(al, z23.y, acc.w);
    }
  }

  acc.x += __shfl_xor_sync(0xffffffffu, acc.x, 16);
  acc.y += __shfl_xor_sync(0xffffffffu, acc.y, 16);
  acc.z += __shfl_xor_sync(0xffffffffu, acc.z, 16);
  acc.w += __shfl_xor_sync(0xffffffffu, acc.w, 16);
  if (lane < 16)
    *(float4*)&out[(size_t)node * OUT_DIM + lane * 4] = acc;
}

// ---------------------------------------------------------------------------
extern "C" void kernel_launch(void* const* d_in, const int* in_sizes, int n_in,
                              void* d_out, int out_size) {
  const float* h_src  = (const float*)d_in[0];
  const float* h_dst  = (const float*)d_in[1];
  const float* W_src  = (const float*)d_in[2];
  const float* W_dst  = (const float*)d_in[3];
  const float* a_w    = (const float*)d_in[4];
  const int*   src_ix = (const int*)d_in[5];
  const int*   dst_ix = (const int*)d_in[6];
  float* out = (float*)d_out;

  cudaFuncSetAttribute(k_zsrc_mma, cudaFuncAttributeMaxDynamicSharedMemorySize, SM_TOT);

  k_init<<<256, 256>>>();
  k_weff<<<1, 256>>>(W_src, W_dst, a_w);
  k_wfr<<<(HO * IN_DIM / 4 + 255) / 256, 256>>>(W_src);
  k_zsrc_mma<<<(N_NODES + BLK_M - 1) / BLK_M, 512, SM_TOT>>>(h_src);
  k_sdst<<<N_NODES / 8, 256>>>(h_dst);
  k_edge1<<<(E_EDGES + 255) / 256, 256>>>(src_ix, dst_ix);
  k_edge2b<<<(N_NODES * 32 + 255) / 256, 256>>>(out);
}

// round 7
// speedup vs baseline: 2.7483x; 1.0148x over previous
#include <cuda_runtime.h>
#include <cuda_fp16.h>
#include <math.h>
#include <stdint.h>

#define N_NODES 100000
#define E_EDGES 1000000
#define IN_DIM  128
#define OUT_DIM 64
#define H_HEADS 2
#define HO      (H_HEADS * OUT_DIM)   // 128

#define BLK_M   128    // nodes per GEMM block
#define ZBLK    ((N_NODES + BLK_M - 1) / BLK_M)   // 782
#define SDBLK   (N_NODES / 16)                    // 6250 (16 warps x 1 node)
#define CAP     64     // max degree slots per dst (Poisson(10): P(deg>=64) ~ 1e-40)
#define PADH    136    // X tile row pad (halves): conflict-free A-frag LDS.32

// ---- scratch (device globals: allocation-free rule) ----
__device__ __half  Z_H[(size_t)N_NODES * HO];       // z_src fp16, 25.6 MB (L2-resident)
__device__ float   S_SRC[N_NODES * H_HEADS];
__device__ float   S_DST[N_NODES * H_HEADS];
__device__ float   W_EFF_SRC[H_HEADS * IN_DIM];
__device__ float   W_EFF_DST[H_HEADS * IN_DIM];
__device__ uint2   W_FRH[HO * IN_DIM / 4];          // W_src fp16, frag-major
__device__ uint2   ENT[(size_t)N_NODES * CAP];      // (half2(ex0,ex1), src) 51.2 MB
__device__ int     COUNT[N_NODES];

// fp16 m16n8k16 MMA, fp32 accumulate (sm_80+ PTX -> Blackwell tensor pipe)
__device__ __forceinline__ void mma_f16(float d[4],
                                        uint32_t a0, uint32_t a1, uint32_t a2, uint32_t a3,
                                        uint32_t b0, uint32_t b1) {
  asm volatile("mma.sync.aligned.m16n8k16.row.col.f32.f16.f16.f32 "
               "{%0,%1,%2,%3}, {%4,%5,%6,%7}, {%8,%9}, {%0,%1,%2,%3};"
               : "+f"(d[0]), "+f"(d[1]), "+f"(d[2]), "+f"(d[3])
               : "r"(a0), "r"(a1), "r"(a2), "r"(a3), "r"(b0), "r"(b1));
}
__device__ __forceinline__ uint32_t h2bits(__half2 h) { return *(uint32_t*)&h; }

// ---------------------------------------------------------------------------
// prep: w_eff (src+dst), W fragment permute (fp16), COUNT zeroing — one launch
// ---------------------------------------------------------------------------
__global__ void k_prep(const float* __restrict__ W_src, const float* __restrict__ W_dst,
                       const float* __restrict__ a_w) {
  int gid = blockIdx.x * blockDim.x + threadIdx.x;
  int stride = gridDim.x * blockDim.x;

  for (int j = gid; j < N_NODES; j += stride) COUNT[j] = 0;

  for (int t = gid; t < H_HEADS * IN_DIM; t += stride) {
    int h = t / IN_DIM, d = t % IN_DIM;
    float as_acc = 0.f, ad_acc = 0.f;
    #pragma unroll 8
    for (int o = 0; o < OUT_DIM; o++) {
      as_acc += a_w[h * 2 * OUT_DIM + o]           * W_src[(h * OUT_DIM + o) * IN_DIM + d];
      ad_acc += a_w[h * 2 * OUT_DIM + OUT_DIM + o] * W_dst[(h * OUT_DIM + o) * IN_DIM + d];
    }
    W_EFF_SRC[t] = as_acc;
    W_EFF_DST[t] = ad_acc;
  }

  // frag-major W permute: o = (tile*8+kk)*32 + lane; lane=(g,q)
  for (int o = gid; o < HO * IN_DIM / 4; o += stride) {
    int lane = o & 31, kk = (o >> 5) & 7, tile = o >> 8;
    int g = lane >> 2, q = lane & 3;
    int n = tile * 8 + g;
    int k0 = kk * 16 + 2 * q;
    const float* wr = &W_src[n * IN_DIM];
    __half2 b0 = __floats2half2_rn(wr[k0],     wr[k0 + 1]);
    __half2 b1 = __floats2half2_rn(wr[k0 + 8], wr[k0 + 9]);
    W_FRH[o] = make_uint2(h2bits(b0), h2bits(b1));
  }
}

// ---------------------------------------------------------------------------
// main fused kernel: blocks [0,ZBLK) do the z_src GEMM (+fused fp32 s_src);
// blocks [ZBLK, ZBLK+SDBLK) stream s_dst (warp per node) — overlaps GEMM tail.
// ---------------------------------------------------------------------------
#define SMX_BYTES (BLK_M * PADH * 2)          // 34816
#define SM_TOT    (SMX_BYTES + 32768)         // 67584

__global__ void __launch_bounds__(512, 2) k_main(const float* __restrict__ h_src,
                                                 const float* __restrict__ h_dst) {
  const int tid  = threadIdx.x;
  const int wid  = tid >> 5;
  const int lane = tid & 31;

  if (blockIdx.x >= ZBLK) {
    // ---- s_dst path: warp per node, fp32-exact ----
    int node = (blockIdx.x - ZBLK) * 16 + wid;
    if (node >= N_NODES) return;
    float4 x = ((const float4*)(h_dst + (size_t)node * IN_DIM))[lane];
    float4 a = ((const float4*)W_EFF_DST)[lane];
    float4 b = ((const float4*)(W_EFF_DST + IN_DIM))[lane];
    float s0 = x.x*a.x + x.y*a.y + x.z*a.z + x.w*a.w;
    float s1 = x.x*b.x + x.y*b.y + x.z*b.z + x.w*b.w;
    #pragma unroll
    for (int m = 16; m; m >>= 1) {
      s0 += __shfl_xor_sync(0xffffffffu, s0, m);
      s1 += __shfl_xor_sync(0xffffffffu, s1, m);
    }
    if (lane == 0) { S_DST[node * 2] = s0; S_DST[node * 2 + 1] = s1; }
    return;
  }

  // ---- z_src GEMM path ----
  extern __shared__ char sm[];
  __half* Xs  = (__half*)sm;                  // [BLK_M][PADH] fp16
  uint2*  Bfr = (uint2*)(sm + SMX_BYTES);     // 4096 fragments, frag-major
  const int nbase = blockIdx.x * BLK_M;

  float4 ws0 = ((const float4*)W_EFF_SRC)[lane];
  float4 ws1 = ((const float4*)(W_EFF_SRC + IN_DIM))[lane];

  // stage X (fp16) + fused fp32 s_src; warp handles one row per iter
  #pragma unroll
  for (int it = 0; it < (BLK_M * 32) / 512; it++) {
    int row = wid + it * 16;
    int gn = nbase + row;
    float4 v = make_float4(0.f, 0.f, 0.f, 0.f);
    if (gn < N_NODES) v = *(const float4*)&h_src[(size_t)gn * IN_DIM + lane * 4];
    float p0 = v.x*ws0.x + v.y*ws0.y + v.z*ws0.z + v.w*ws0.w;
    float p1 = v.x*ws1.x + v.y*ws1.y + v.z*ws1.z + v.w*ws1.w;
    #pragma unroll
    for (int m = 16; m; m >>= 1) {
      p0 += __shfl_xor_sync(0xffffffffu, p0, m);
      p1 += __shfl_xor_sync(0xffffffffu, p1, m);
    }
    if (lane == 0 && gn < N_NODES) { S_SRC[gn * 2] = p0; S_SRC[gn * 2 + 1] = p1; }
    __half2 h01 = __floats2half2_rn(v.x, v.y);
    __half2 h23 = __floats2half2_rn(v.z, v.w);
    *(uint2*)&Xs[row * PADH + lane * 4] = make_uint2(h2bits(h01), h2bits(h23));
  }
  // stage W fragments (32KB contiguous copy)
  {
    const uint4* src = (const uint4*)W_FRH;
    uint4* dst = (uint4*)Bfr;
    #pragma unroll
    for (int it = 0; it < 2048 / 512; it++)
      dst[tid + it * 512] = src[tid + it * 512];
  }
  __syncthreads();

  const int wm = wid >> 1;          // m-tile: nodes wm*16 .. +15
  const int wn = wid & 1;           // n-half: cols wn*64 .. +63
  const int g  = lane >> 2;
  const int q  = lane & 3;

  float d[8][4];
  #pragma unroll
  for (int j = 0; j < 8; j++)
    #pragma unroll
    for (int c = 0; c < 4; c++) d[j][c] = 0.f;

  const __half* Ar0 = &Xs[(wm * 16 + g) * PADH];
  const __half* Ar1 = Ar0 + 8 * PADH;

  #pragma unroll
  for (int kk = 0; kk < 8; kk++) {
    int c = kk * 16 + 2 * q;
    uint32_t a0 = *(const uint32_t*)&Ar0[c];
    uint32_t a1 = *(const uint32_t*)&Ar1[c];
    uint32_t a2 = *(const uint32_t*)&Ar0[c + 8];
    uint32_t a3 = *(const uint32_t*)&Ar1[c + 8];
    #pragma unroll
    for (int j = 0; j < 8; j++) {
      uint2 b = Bfr[((wn * 8 + j) * 8 + kk) * 32 + lane];   // contiguous 256B/warp
      mma_f16(d[j], a0, a1, a2, a3, b.x, b.y);
    }
  }

  // epilogue: store Z as fp16
  int r0 = nbase + wm * 16 + g;
  int r1 = r0 + 8;
  bool v0 = (r0 < N_NODES), v1 = (r1 < N_NODES);
  #pragma unroll
  for (int j = 0; j < 8; j++) {
    int col = (wn * 8 + j) * 8 + q * 2;
    if (v0) *(__half2*)&Z_H[(size_t)r0 * HO + col] = __floats2half2_rn(d[j][0], d[j][1]);
    if (v1) *(__half2*)&Z_H[(size_t)r1 * HO + col] = __floats2half2_rn(d[j][2], d[j][3]);
  }
}

// ---------------------------------------------------------------------------
// edge pass: ex = exp(leaky_relu(s_src[src]+s_dst[dst])) (max-free, bounded:
// |e| <~ 7 -> ex in [1e-3, 1.1e3], comfortably in half range).
// One atomic slot-grab; single 8B ENT store. NO denominator atomics.
// ---------------------------------------------------------------------------
__global__ void k_edge1(const int* __restrict__ src_idx, const int* __restrict__ dst_idx) {
  int e = blockIdx.x * blockDim.x + threadIdx.x;
  if (e >= E_EDGES) return;
  int s = src_idx[e], d = dst_idx[e];
  float2 ss = *(const float2*)&S_SRC[s * 2];
  float2 sd = *(const float2*)&S_DST[d * 2];
  float e0 = ss.x + sd.x; e0 = e0 > 0.f ? e0 : 0.01f * e0;
  float e1 = ss.y + sd.y; e1 = e1 > 0.f ? e1 : 0.01f * e1;
  float x0 = expf(e0), x1 = expf(e1);
  int c = atomicAdd(&COUNT[d], 1);
  if (c < CAP)
    ENT[(size_t)d * CAP + c] = make_uint2(h2bits(__floats2half2_rn(x0, x1)), (uint32_t)s);
}

// ---------------------------------------------------------------------------
// gather pass: warp per dst node. Accumulate UNNORMALIZED sum(ex*z) and the
// denominators in registers; normalize once at the end. 2-way ILP on z loads.
// ---------------------------------------------------------------------------
__global__ void __launch_bounds__(256) k_edge2b(float* __restrict__ out) {
  int node = (blockIdx.x * blockDim.x + threadIdx.x) >> 5;
  int lane = threadIdx.x & 31;
  if (node >= N_NODES) return;

  int deg = COUNT[node];
  deg = deg < CAP ? deg : CAP;

  float dn0 = 0.f, dn1 = 0.f;
  float4 acc = make_float4(0.f, 0.f, 0.f, 0.f);
  const size_t base = (size_t)node * CAP;
  const bool h0 = (lane < 16);

  for (int c0 = 0; c0 < deg; c0 += 32) {
    int c = c0 + lane;
    uint2 ent = make_uint2(0u, 0u);
    if (c < deg) ent = ENT[base + c];
    int cnt = deg - c0; cnt = cnt < 32 ? cnt : 32;
    for (int j = 0; j < cnt; j += 2) {
      // edge A
      uint32_t exa = __shfl_sync(0xffffffffu, ent.x, j);
      uint32_t sa  = __shfl_sync(0xffffffffu, ent.y, j);
      // edge B (may be out of range)
      uint32_t exb = __shfl_sync(0xffffffffu, ent.x, j + 1);
      uint32_t sb  = __shfl_sync(0xffffffffu, ent.y, j + 1);
      bool hasB = (j + 1 < cnt);

      float2 xa = __half22float2(*(__half2*)&exa);
      uint2 rawA = *(const uint2*)&Z_H[(size_t)sa * HO + lane * 4];
      uint2 rawB = hasB ? *(const uint2*)&Z_H[(size_t)sb * HO + lane * 4]
                        : make_uint2(0u, 0u);

      dn0 += xa.x; dn1 += xa.y;
      float ala = h0 ? xa.x : xa.y;
      float2 a01 = __half22float2(*(__half2*)&rawA.x);
      float2 a23 = __half22float2(*(__half2*)&rawA.y);
      acc.x = fmaf(ala, a01.x, acc.x);
      acc.y = fmaf(ala, a01.y, acc.y);
      acc.z = fmaf(ala, a23.x, acc.z);
      acc.w = fmaf(ala, a23.y, acc.w);

      if (hasB) {
        float2 xb = __half22float2(*(__half2*)&exb);
        dn0 += xb.x; dn1 += xb.y;
        float alb = h0 ? xb.x : xb.y;
        float2 b01 = __half22float2(*(__half2*)&rawB.x);
        float2 b23 = __half22float2(*(__half2*)&rawB.y);
        acc.x = fmaf(alb, b01.x, acc.x);
        acc.y = fmaf(alb, b01.y, acc.y);
        acc.z = fmaf(alb, b23.x, acc.z);
        acc.w = fmaf(alb, b23.y, acc.w);
      }
    }
  }

  // normalize per head (deg==0 -> inv=0 -> stores exact zeros)
  float inv0 = dn0 > 0.f ? 1.f / dn0 : 0.f;
  float inv1 = dn1 > 0.f ? 1.f / dn1 : 0.f;
  float inv = h0 ? inv0 : inv1;
  acc.x *= inv; acc.y *= inv; acc.z *= inv; acc.w *= inv;

  // combine the two heads: lane L (<16, h0) pairs with lane L+16 (h1, same o)
  acc.x += __shfl_xor_sync(0xffffffffu, acc.x, 16);
  acc.y += __shfl_xor_sync(0xffffffffu, acc.y, 16);
  acc.z += __shfl_xor_sync(0xffffffffu, acc.z, 16);
  acc.w += __shfl_xor_sync(0xffffffffu, acc.w, 16);
  if (lane < 16)
    *(float4*)&out[(size_t)node * OUT_DIM + lane * 4] = acc;
}

// ---------------------------------------------------------------------------
extern "C" void kernel_launch(void* const* d_in, const int* in_sizes, int n_in,
                              void* d_out, int out_size) {
  const float* h_src  = (const float*)d_in[0];
  const float* h_dst  = (const float*)d_in[1];
  const float* W_src  = (const float*)d_in[2];
  const float* W_dst  = (const float*)d_in[3];
  const float* a_w    = (const float*)d_in[4];
  const int*   src_ix = (const int*)d_in[5];
  const int*   dst_ix = (const int*)d_in[6];
  float* out = (float*)d_out;

  cudaFuncSetAttribute(k_main, cudaFuncAttributeMaxDynamicSharedMemorySize, SM_TOT);

  k_prep<<<256, 256>>>(W_src, W_dst, a_w);
  k_main<<<ZBLK + SDBLK, 512, SM_TOT>>>(h_src, h_dst);
  k_edge1<<<(E_EDGES + 255) / 256, 256>>>(src_ix, dst_ix);
  k_edge2b<<<(N_NODES * 32 + 255) / 256, 256>>>(out);
}